// round 15
// baseline (speedup 1.0000x reference)
#include <cuda_runtime.h>
#include <cuda_fp16.h>

typedef unsigned int u32;

#define B_  8
#define C_  256
#define H_  128
#define W_  128
#define HW  16384
#define NHD 16
#define DH  16

// ---------------- fp32 stage buffers (lifetime-aliased) ----------------------
__device__ float g_bufA[(size_t)B_ * C_ * HW];   // pre out  -> mix
__device__ float g_bufB[(size_t)B_ * C_ * HW];   // loc
__device__ float g_bufC[(size_t)B_ * 768 * HW];  // qkv out  -> dwo
__device__ float g_bufD[(size_t)B_ * C_ * HW];   // att

// ------------- packed fp16-pair activations (single-rounded) -----------------
#define APACK ((size_t)B_ * 128 * HW)
__device__ u32 g_xH[APACK];   // from x       (pre + qkv input)
__device__ u32 g_pH[APACK];   // from pre out (dil input), then dwo (pw input)

// ------------- fp16 weights, m-major rows (for ldmatrix A path) --------------
// 1x1: [M][256] halves;  dil: [group][tap 9][m 96][k 96] halves (zero-padded)
__device__ __half g_wPreH[256 * 256];
__device__ __half g_wQkvH[768 * 256];
__device__ __half g_wPwH [256 * 256];
__device__ __half g_wDilH[3 * 9 * 96 * 96];

// ---------------- helpers ----------------------------------------------------
__device__ __forceinline__ u32 pack_h2(float x0, float x1) {
    __half h0 = __float2half_rn(x0);
    __half h1 = __float2half_rn(x1);
    return (u32)__half_as_ushort(h0) | ((u32)__half_as_ushort(h1) << 16);
}
__device__ __forceinline__ u32 smem_u32p(const void* p) {
    u32 a;
    asm("{ .reg .u64 t; cvta.to.shared.u64 t, %1; cvt.u32.u64 %0, t; }" : "=r"(a) : "l"(p));
    return a;
}
__device__ __forceinline__ void ldsm_x4(u32* r, u32 addr) {
    asm volatile("ldmatrix.sync.aligned.m8n8.x4.shared.b16 {%0,%1,%2,%3}, [%4];"
                 : "=r"(r[0]), "=r"(r[1]), "=r"(r[2]), "=r"(r[3]) : "r"(addr));
}
__device__ __forceinline__ void mma16816(float* d, const u32* a, const u32* b) {
    asm volatile(
        "mma.sync.aligned.m16n8k16.row.col.f32.f16.f16.f32 "
        "{%0,%1,%2,%3}, {%4,%5,%6,%7}, {%8,%9}, {%0,%1,%2,%3};"
        : "+f"(d[0]), "+f"(d[1]), "+f"(d[2]), "+f"(d[3])
        : "r"(a[0]), "r"(a[1]), "r"(a[2]), "r"(a[3]), "r"(b[0]), "r"(b[1]));
}

// -------- activation pack: fp32 [B][256][HW] -> fp16-pair u32 [B][128][HW] ---
__global__ __launch_bounds__(256) void pack_act(
    const float* __restrict__ in, u32* __restrict__ hp)
{
    const size_t idx = (size_t)blockIdx.x * 256 + threadIdx.x; // B*128*(HW/4)
    const size_t p4  = idx & 4095;
    const size_t t   = idx >> 12;              // b*128 + c2
    const int    c2  = (int)(t & 127);
    const int    b   = (int)(t >> 7);
    const float* r0  = in + ((size_t)b * C_ + 2 * c2) * HW + p4 * 4;
    float4 a = *(const float4*)r0;
    float4 c = *(const float4*)(r0 + HW);
    *(uint4*)(hp + t * HW + p4 * 4) =
        make_uint4(pack_h2(a.x, c.x), pack_h2(a.y, c.y),
                   pack_h2(a.z, c.z), pack_h2(a.w, c.w));
}

// ---------------- 1x1 weight pack: fp32 [M][256] -> fp16 [M][256] ------------
__global__ __launch_bounds__(256) void pack_w16(
    const float* __restrict__ W, __half* __restrict__ o, int n)
{
    const int idx = blockIdx.x * 256 + threadIdx.x;
    if (idx < n) o[idx] = __float2half_rn(W[idx]);
}

// ------ dil weight pack: W[Cg][Cg][3][3] -> [9][96][96] halves, m-major ------
__global__ __launch_bounds__(256) void pack_wdil16(
    const float* __restrict__ W, __half* __restrict__ o, int Cg)
{
    const int idx = blockIdx.x * 256 + threadIdx.x;
    if (idx >= 9 * 96 * 96) return;
    const int k   = idx % 96;
    const int m   = (idx / 96) % 96;
    const int tap = idx / (96 * 96);
    float v = 0.f;
    if (m < Cg && k < Cg) v = W[((size_t)m * Cg + k) * 9 + tap];
    o[idx] = __float2half_rn(v);
}

// =============================================================================
// 1x1 conv GEMM (K=256), pure fp16, ldmatrix-A, double-buffered.
// Block: 128M x 256N, 8 warps, warp 64x64.  grid: (HW/256, Mtot/128, B).
// =============================================================================
__global__ __launch_bounds__(256, 1) void gemm1x1_mma(
    const __half* __restrict__ wHp, int Mtot,
    const u32* __restrict__ aHp,
    float* __restrict__ out, const float* __restrict__ bnp, int Cout, int use_bn)
{
    __shared__ __align__(16) char AsRaw[2][128 * 48];   // m-major rows, 48B stride
    __shared__ u32 Bs[2][8][260];
    const int b    = blockIdx.z;
    const int m0   = blockIdx.y * 128, n0 = blockIdx.x * 256;
    const int tid  = threadIdx.x, wid = tid >> 5, lane = tid & 31;
    const int wm   = (wid >> 2) * 64, wn = (wid & 3) * 64;
    const int g    = lane >> 2, q = lane & 3;
    const u32*    aB = aHp + (size_t)b * 128 * HW + n0;
    const __half* wB = wHp + (size_t)m0 * 256;

    // ldmatrix per-lane offset within an i-tile
    const int lRow = (lane & 7) + ((lane >> 3) & 1) * 8;   // 0..15
    const int lKof = (lane >> 4) * 16;                     // 0 or 16 bytes
    const u32 asBase = smem_u32p(AsRaw);

    // A loader: 128 rows x 32B; 2 threads per row
    const int am = tid >> 1, ac = tid & 1;
    // B loader: 8 rows x 256 u32; 2 uint4 per thread
    const int lrow = tid >> 6, lcol = (tid & 63) * 4;

    float acc[4][8][4];
#pragma unroll
    for (int i = 0; i < 4; i++)
#pragma unroll
        for (int j = 0; j < 8; j++)
#pragma unroll
            for (int r = 0; r < 4; r++) acc[i][j][r] = 0.f;

    uint4 rAv, rB0, rB1;
    auto loadg = [&](int kk) {
        rAv = *(const uint4*)&wB[(size_t)am * 256 + kk * 16 + ac * 8];
        rB0 = *(const uint4*)&aB[(size_t)(kk * 8 + lrow) * HW + lcol];
        rB1 = *(const uint4*)&aB[(size_t)(kk * 8 + lrow + 4) * HW + lcol];
    };
    auto stores = [&](int st) {
        *(uint4*)(AsRaw[st] + am * 48 + ac * 16) = rAv;
        *(uint4*)&Bs[st][lrow][lcol]     = rB0;
        *(uint4*)&Bs[st][lrow + 4][lcol] = rB1;
    };

    loadg(0);
    stores(0);
    __syncthreads();

    for (int kk = 0; kk < 16; kk++) {
        const int cur = kk & 1;
        if (kk < 15) loadg(kk + 1);

        u32 aq[4][4], bq[8][2];
#pragma unroll
        for (int i = 0; i < 4; i++) {
            const u32 addr = asBase + cur * (128 * 48)
                           + (wm + i * 16 + lRow) * 48 + lKof;
            ldsm_x4(aq[i], addr);
        }
#pragma unroll
        for (int j = 0; j < 8; j++) {
            const int nb = wn + j * 8 + g;
            bq[j][0] = Bs[cur][q][nb];
            bq[j][1] = Bs[cur][q + 4][nb];
        }
#pragma unroll
        for (int i = 0; i < 4; i++)
#pragma unroll
            for (int j = 0; j < 8; j++)
                mma16816(acc[i][j], aq[i], bq[j]);

        if (kk < 15) {
            stores(cur ^ 1);
            __syncthreads();
        }
    }

#pragma unroll
    for (int i = 0; i < 4; i++)
#pragma unroll
        for (int half = 0; half < 2; half++) {
            const int co = m0 + wm + i * 16 + g + half * 8;
            float scale = 1.f, shift = 0.f;
            if (use_bn) {
                const float gg = bnp[co],            be = bnp[Cout + co];
                const float mu = bnp[2 * Cout + co], va = bnp[3 * Cout + co];
                scale = gg * rsqrtf(va + 1e-5f);
                shift = be - mu * scale;
            }
            float* o = out + ((size_t)b * Cout + co) * HW + n0 + wn + 2 * q;
#pragma unroll
            for (int j = 0; j < 8; j++) {
                float2 v;
                v.x = acc[i][j][half * 2]     * scale + shift;
                v.y = acc[i][j][half * 2 + 1] * scale + shift;
                *(float2*)&o[j * 8] = v;
            }
        }
}

// =============================================================================
// Dilated 3x3 conv GEMM, tap-outer, pure fp16, ldmatrix-A, double-buffered.
// Block: 96M x 128N (one image row).  54 pipelined K-steps.
// grid: (H, 1, B), block 256.
// =============================================================================
__global__ __launch_bounds__(256) void dil_mma(
    const __half* __restrict__ wHp,  // [9][96][96] halves, m-major
    const u32* __restrict__ aHp,     // packed pre (fp16 pairs, channel-major)
    int basePair, int pairsValid, int dil, int Cg,
    float* __restrict__ out, int coBase, const float* __restrict__ bnp)
{
    __shared__ __align__(16) char AsRaw[2][96 * 48];
    __shared__ u32 Bs[2][8][132];
    const int b    = blockIdx.z;
    const int h    = blockIdx.x;
    const int tid  = threadIdx.x, wid = tid >> 5, lane = tid & 31;
    const int wm   = (wid >> 2) * 48, wn = (wid & 3) * 32;
    const int g    = lane >> 2, q = lane & 3;
    const u32* aB = aHp + (size_t)b * 128 * HW;

    const int lRow = (lane & 7) + ((lane >> 3) & 1) * 8;
    const int lKof = (lane >> 4) * 16;
    const u32 asBase = smem_u32p(AsRaw);

    const int am = tid >> 1, ac = tid & 1;           // A: rows 0..95 (tid<192)
    const int bk0 = tid >> 7,  bn0v = tid & 127;     // B: 4 u32/thread

    float acc[3][4][4];
#pragma unroll
    for (int i = 0; i < 3; i++)
#pragma unroll
        for (int j = 0; j < 4; j++)
#pragma unroll
            for (int r = 0; r < 4; r++) acc[i][j][r] = 0.f;

    uint4 rAv;
    u32 rB[4];
    auto loadg = [&](int tap, int ks) {
        const int dy = tap / 3 - 1, dx = tap % 3 - 1;
        const int sh = h + dy * dil;
        const bool rowOk = (sh >= 0 && sh < H_);
        if (tid < 192)
            rAv = *(const uint4*)&wHp[((size_t)tap * 96 + am) * 96 + ks * 16 + ac * 8];
#pragma unroll
        for (int s = 0; s < 4; s++) {
            const int k2 = bk0 + s * 2;
            const int pr = ks * 8 + k2;
            const int sp = bn0v + dx * dil;
            u32 v = 0u;
            if (pr < pairsValid && rowOk && sp >= 0 && sp < W_)
                v = aB[(size_t)(basePair + pr) * HW + sh * W_ + sp];
            rB[s] = v;
        }
    };
    auto stores = [&](int st) {
        if (tid < 192)
            *(uint4*)(AsRaw[st] + am * 48 + ac * 16) = rAv;
#pragma unroll
        for (int s = 0; s < 4; s++)
            Bs[st][bk0 + s * 2][bn0v] = rB[s];
    };

    loadg(0, 0);
    stores(0);
    __syncthreads();

    int tap = 0, ks = 0;
    for (int step = 0; step < 54; step++) {
        const int cur = step & 1;
        const int ntap = (ks == 5) ? tap + 1 : tap;
        const int nks  = (ks == 5) ? 0 : ks + 1;
        if (step < 53) loadg(ntap, nks);

        u32 aq[3][4], bq[4][2];
#pragma unroll
        for (int i = 0; i < 3; i++) {
            const u32 addr = asBase + cur * (96 * 48)
                           + (wm + i * 16 + lRow) * 48 + lKof;
            ldsm_x4(aq[i], addr);
        }
#pragma unroll
        for (int j = 0; j < 4; j++) {
            const int nb = wn + j * 8 + g;
            bq[j][0] = Bs[cur][q][nb];
            bq[j][1] = Bs[cur][q + 4][nb];
        }
#pragma unroll
        for (int i = 0; i < 3; i++)
#pragma unroll
            for (int j = 0; j < 4; j++)
                mma16816(acc[i][j], aq[i], bq[j]);

        if (step < 53) {
            stores(cur ^ 1);
            __syncthreads();
        }
        tap = ntap; ks = nks;
    }

#pragma unroll
    for (int i = 0; i < 3; i++)
#pragma unroll
        for (int half = 0; half < 2; half++) {
            const int co = wm + i * 16 + g + half * 8;
            if (co < Cg) {
                const float gg = bnp[co],          be = bnp[Cg + co];
                const float mu = bnp[2 * Cg + co], va = bnp[3 * Cg + co];
                const float scale = gg * rsqrtf(va + 1e-5f);
                const float shift = be - mu * scale;
                float* o = out + ((size_t)b * C_ + coBase + co) * HW + h * W_ + wn + 2 * q;
#pragma unroll
                for (int j = 0; j < 4; j++) {
                    float2 v;
                    v.x = acc[i][j][half * 2]     * scale + shift;
                    v.y = acc[i][j][half * 2 + 1] * scale + shift;
                    *(float2*)&o[j * 8] = v;
                }
            }
        }
}

// =============================================================================
// Windowed attention (unchanged, verified).  grid: (B*256, NH), block 64
// =============================================================================
__global__ __launch_bounds__(64) void attn_kernel(
    const float* __restrict__ qkv, const float* __restrict__ rpb,
    float* __restrict__ out)
{
    const int win  = blockIdx.x;
    const int head = blockIdx.y;
    const int b    = win >> 8;
    const int wy   = (win >> 4) & 15;
    const int wx   = win & 15;
    const int i    = threadIdx.x;
    const int yi   = i >> 3, xi = i & 7;
    const int py   = wy * 8 + yi, px = wx * 8 + xi;

    __shared__ float ks[64][16];
    __shared__ float vs[64][16];
    __shared__ float bias_s[232];

    const size_t pix = (size_t)py * W_ + px;
    const float* qb  = qkv + ((size_t)b * 768 + head * DH) * HW + pix;

    float qv[16];
#pragma unroll
    for (int dd = 0; dd < 16; dd++) {
        qv[dd]    = qb[(size_t)dd * HW];
        ks[i][dd] = qb[(size_t)(256 + dd) * HW];
        vs[i][dd] = qb[(size_t)(512 + dd) * HW];
    }
    for (int t = i; t < 225; t += 64) bias_s[t] = rpb[t * NHD + head];
    __syncthreads();

    float s[64];
    float mx = -1e30f;
#pragma unroll
    for (int j = 0; j < 64; j++) {
        const float4* kr = (const float4*)&ks[j][0];
        float4 k0 = kr[0], k1 = kr[1], k2 = kr[2], k3 = kr[3];
        float dot = qv[0]  * k0.x + qv[1]  * k0.y + qv[2]  * k0.z + qv[3]  * k0.w
                  + qv[4]  * k1.x + qv[5]  * k1.y + qv[6]  * k1.z + qv[7]  * k1.w
                  + qv[8]  * k2.x + qv[9]  * k2.y + qv[10] * k2.z + qv[11] * k2.w
                  + qv[12] * k3.x + qv[13] * k3.y + qv[14] * k3.z + qv[15] * k3.w;
        const int yj = j >> 3, xj = j & 7;
        float val = dot * 0.25f + bias_s[(yi - yj + 7) * 15 + (xi - xj + 7)];
        s[j] = val;
        mx = fmaxf(mx, val);
    }
    float sum = 0.f;
#pragma unroll
    for (int j = 0; j < 64; j++) { float e = __expf(s[j] - mx); s[j] = e; sum += e; }
    const float inv = 1.f / sum;

    float4 o0 = {0, 0, 0, 0}, o1 = o0, o2 = o0, o3 = o0;
#pragma unroll
    for (int j = 0; j < 64; j++) {
        const float p = s[j];
        const float4* vr = (const float4*)&vs[j][0];
        float4 v0 = vr[0], v1 = vr[1], v2 = vr[2], v3 = vr[3];
        o0.x += p * v0.x; o0.y += p * v0.y; o0.z += p * v0.z; o0.w += p * v0.w;
        o1.x += p * v1.x; o1.y += p * v1.y; o1.z += p * v1.z; o1.w += p * v1.w;
        o2.x += p * v2.x; o2.y += p * v2.y; o2.z += p * v2.z; o2.w += p * v2.w;
        o3.x += p * v3.x; o3.y += p * v3.y; o3.z += p * v3.z; o3.w += p * v3.w;
    }

    float ov[16] = {o0.x, o0.y, o0.z, o0.w, o1.x, o1.y, o1.z, o1.w,
                    o2.x, o2.y, o2.z, o2.w, o3.x, o3.y, o3.z, o3.w};
    float* ob = out + ((size_t)b * C_ + head * DH) * HW + pix;
#pragma unroll
    for (int dd = 0; dd < 16; dd++) ob[(size_t)dd * HW] = ov[dd] * inv;
}

// =============================================================================
__global__ __launch_bounds__(256) void pooladd_kernel(
    const float* __restrict__ att, const float* __restrict__ loc,
    float* __restrict__ out)
{
    const size_t idx = (size_t)blockIdx.x * 256 + threadIdx.x;
    const int w = (int)(idx & (W_ - 1));
    const int h = (int)((idx >> 7) & (H_ - 1));
    const size_t bc = idx >> 14;
    const float* p = att + (bc << 14);
    float sx = 0.f, sy = 0.f;
#pragma unroll
    for (int t = -3; t <= 4; t++) {
        const int r = h + t;
        if (r >= 0 && r <= H_) { const int rr = (r == H_) ? H_ - 2 : r; sx += p[rr * W_ + w]; }
        const int c2 = w + t;
        if (c2 >= 0 && c2 <= W_) { const int cc = (c2 == W_) ? W_ - 2 : c2; sy += p[h * W_ + cc]; }
    }
    out[idx] = (sx + sy) * 0.125f + loc[idx];
}

// =============================================================================
__global__ __launch_bounds__(256) void dw_kernel(
    const float* __restrict__ in, const float* __restrict__ wdw,
    float* __restrict__ out)
{
    __shared__ float tile[23][48];
    __shared__ float wt[64];
    const int bc = blockIdx.z;
    const int h0 = blockIdx.y * 16, w0 = blockIdx.x * 16;
    const int tx = threadIdx.x, ty = threadIdx.y;
    const int tid = ty * 16 + tx;
    const float* p = in + (size_t)bc * HW;

    if (tid < 64) wt[tid] = wdw[(size_t)(bc & 255) * 64 + tid];
    for (int t = tid; t < 23 * 23; t += 256) {
        const int r = h0 - 3 + t / 23;
        const int s = w0 - 3 + t % 23;
        float v = 0.f;
        if (r >= 0 && r <= H_ && s >= 0 && s <= W_) {
            const int rr = (r == H_) ? H_ - 2 : r;
            const int ss = (s == W_) ? W_ - 2 : s;
            v = p[rr * W_ + ss];
        }
        tile[t / 23][t % 23] = v;
    }
    __syncthreads();

    float acc = 0.f;
#pragma unroll
    for (int u = 0; u < 8; u++)
#pragma unroll
        for (int v = 0; v < 8; v++)
            acc = fmaf(wt[u * 8 + v], tile[ty + u][tx + v], acc);
    out[(size_t)bc * HW + (h0 + ty) * W_ + w0 + tx] = acc;
}

// =============================================================================
extern "C" void kernel_launch(void* const* d_in, const int* in_sizes, int n_in,
                              void* d_out, int out_size)
{
    const float* x       = (const float*)d_in[0];
    const float* w_pre   = (const float*)d_in[1];
    const float* bn_pre  = (const float*)d_in[2];
    const float* w_l1    = (const float*)d_in[3];
    const float* bn_l1   = (const float*)d_in[4];
    const float* w_l2    = (const float*)d_in[5];
    const float* bn_l2   = (const float*)d_in[6];
    const float* w_l3    = (const float*)d_in[7];
    const float* bn_l3   = (const float*)d_in[8];
    const float* w_qkv   = (const float*)d_in[9];
    const float* rpb     = (const float*)d_in[10];
    const float* w_dw    = (const float*)d_in[11];
    const float* w_pw    = (const float*)d_in[12];
    const float* bn_proj = (const float*)d_in[13];
    float* out = (float*)d_out;

    float *bufA, *bufB, *bufC, *bufD;
    cudaGetSymbolAddress((void**)&bufA, g_bufA);
    cudaGetSymbolAddress((void**)&bufB, g_bufB);
    cudaGetSymbolAddress((void**)&bufC, g_bufC);
    cudaGetSymbolAddress((void**)&bufD, g_bufD);
    u32 *xH, *pH;
    cudaGetSymbolAddress((void**)&xH, g_xH);
    cudaGetSymbolAddress((void**)&pH, g_pH);
    __half *wPre, *wQkv, *wPw, *wDil;
    cudaGetSymbolAddress((void**)&wPre, g_wPreH);
    cudaGetSymbolAddress((void**)&wQkv, g_wQkvH);
    cudaGetSymbolAddress((void**)&wPw,  g_wPwH);
    cudaGetSymbolAddress((void**)&wDil, g_wDilH);

    float* pre  = bufA;
    float* loc  = bufB;
    float* qkvb = bufC;
    float* att  = bufD;
    float* mix  = bufA;
    float* dwo  = bufC;
    u32*   dH   = pH;    // stage-7 pack reuses pre-pack buffer (disjoint lifetime)

    const int DW = 9 * 96 * 96;                      // 82944 per group
    const int packBlocks = (int)(APACK / 4 / 256);   // 16384

    // ---- weight + input packing ----
    pack_w16<<<(256 * 256 + 255) / 256, 256>>>(w_pre, wPre, 256 * 256);
    pack_w16<<<(768 * 256 + 255) / 256, 256>>>(w_qkv, wQkv, 768 * 256);
    pack_w16<<<(256 * 256 + 255) / 256, 256>>>(w_pw,  wPw,  256 * 256);
    pack_wdil16<<<(DW + 255) / 256, 256>>>(w_l1, wDil,          86);
    pack_wdil16<<<(DW + 255) / 256, 256>>>(w_l2, wDil + DW,     86);
    pack_wdil16<<<(DW + 255) / 256, 256>>>(w_l3, wDil + 2 * DW, 84);
    pack_act<<<packBlocks, 256>>>(x, xH);

    // ---- 1. pre 1x1 + BN ----
    gemm1x1_mma<<<dim3(HW / 256, 2, B_), 256>>>(wPre, 256, xH, pre, bn_pre, 256, 1);
    pack_act<<<packBlocks, 256>>>(pre, pH);

    // ---- 2. dilated convs + BN ----
    dil_mma<<<dim3(H_, 1, B_), 256>>>(wDil,          pH,  0, 43, 1, 86, loc,   0, bn_l1);
    dil_mma<<<dim3(H_, 1, B_), 256>>>(wDil + DW,     pH, 43, 43, 2, 86, loc,  86, bn_l2);
    dil_mma<<<dim3(H_, 1, B_), 256>>>(wDil + 2 * DW, pH, 86, 42, 3, 84, loc, 172, bn_l3);

    // ---- 3. qkv 1x1 ----
    gemm1x1_mma<<<dim3(HW / 256, 6, B_), 256>>>(wQkv, 768, xH, qkvb, bn_pre, 768, 0);

    // ---- 4. attention ----
    attn_kernel<<<dim3(B_ * 256, NHD), 64>>>(qkvb, rpb, att);

    // ---- 5. pool + add local ----
    pooladd_kernel<<<dim3((unsigned)((size_t)B_ * C_ * HW / 256)), 256>>>(att, loc, mix);

    // ---- 6. depthwise 8x8 ----
    dw_kernel<<<dim3(8, 8, B_ * C_), dim3(16, 16)>>>(mix, w_dw, dwo);

    // ---- 7. pw 1x1 + BN ----
    pack_act<<<packBlocks, 256>>>(dwo, dH);
    gemm1x1_mma<<<dim3(HW / 256, 2, B_), 256>>>(wPw, 256, dH, out, bn_proj, 256, 1);
}

// round 17
// speedup vs baseline: 1.0391x; 1.0391x over previous
#include <cuda_runtime.h>
#include <cuda_fp16.h>

typedef unsigned int u32;

#define B_  8
#define C_  256
#define H_  128
#define W_  128
#define HW  16384
#define NHD 16
#define DH  16

// ---------------- fp32 stage buffers (lifetime-aliased) ----------------------
__device__ float g_bufB[(size_t)B_ * C_ * HW];   // loc
__device__ float g_bufC[(size_t)B_ * 768 * HW];  // qkv out -> dwo
__device__ float g_bufD[(size_t)B_ * C_ * HW];   // att
__device__ float g_bufA[(size_t)B_ * C_ * HW];   // mix

// ------------- packed fp16-pair activations (single-rounded) -----------------
#define APACK ((size_t)B_ * 128 * HW)
__device__ u32 g_xH[APACK];   // from x  (pre + qkv input)
__device__ u32 g_pH[APACK];   // pre out (written by fused gemm epilogue), then dwo

// ------------- packed fp16-pair weights (single-rounded) ---------------------
// 1x1: [K/2=128][M]; dil: [group][tap 9][pair-row 48][m 128 padded]
__device__ u32 g_wPreH[128 * 256];
__device__ u32 g_wQkvH[128 * 768];
__device__ u32 g_wPwH [128 * 256];
__device__ u32 g_wDilH[3 * 9 * 48 * 128];

// ---------------- fp16 pack helper -------------------------------------------
__device__ __forceinline__ u32 pack_h2(float x0, float x1) {
    __half h0 = __float2half_rn(x0);
    __half h1 = __float2half_rn(x1);
    return (u32)__half_as_ushort(h0) | ((u32)__half_as_ushort(h1) << 16);
}

// -------- activation pack: fp32 [B][256][HW] -> fp16-pair u32 [B][128][HW] ---
__global__ __launch_bounds__(256) void pack_act(
    const float* __restrict__ in, u32* __restrict__ hp)
{
    const size_t idx = (size_t)blockIdx.x * 256 + threadIdx.x; // B*128*(HW/4)
    const size_t p4  = idx & 4095;
    const size_t t   = idx >> 12;              // b*128 + c2
    const int    c2  = (int)(t & 127);
    const int    b   = (int)(t >> 7);
    const float* r0  = in + ((size_t)b * C_ + 2 * c2) * HW + p4 * 4;
    float4 a = *(const float4*)r0;
    float4 c = *(const float4*)(r0 + HW);
    *(uint4*)(hp + t * HW + p4 * 4) =
        make_uint4(pack_h2(a.x, c.x), pack_h2(a.y, c.y),
                   pack_h2(a.z, c.z), pack_h2(a.w, c.w));
}

// ---------------- 1x1 weight pack: W[M][256] -> [128][M] fp16 pairs ----------
__global__ __launch_bounds__(256) void pack_w1x1(
    const float* __restrict__ W, u32* __restrict__ hp, int M)
{
    const int idx = blockIdx.x * 256 + threadIdx.x;
    if (idx >= M * 128) return;
    const int m = idx % M, k2 = idx / M;
    hp[(size_t)k2 * M + m] = pack_h2(W[m * 256 + 2 * k2], W[m * 256 + 2 * k2 + 1]);
}

// ------ dil weight pack (all 3 groups): -> [3][9][48][128] fp16 pairs --------
__global__ __launch_bounds__(256) void pack_wdil_all(
    const float* __restrict__ W0, const float* __restrict__ W1,
    const float* __restrict__ W2, u32* __restrict__ hp)
{
    const int idx = blockIdx.x * 256 + threadIdx.x;
    if (idx >= 3 * 9 * 48 * 128) return;
    const int grp = idx / (9 * 48 * 128);
    const int rem = idx - grp * (9 * 48 * 128);
    const int m  = rem & 127;
    const int r  = rem >> 7;
    const int k2 = r % 48;
    const int t  = r / 48;
    const int Cg = (grp == 2) ? 84 : 86;
    const float* W = (grp == 0) ? W0 : (grp == 1) ? W1 : W2;
    float a = 0.f, b = 0.f;
    if (m < Cg) {
        if (2 * k2     < Cg) a = W[((size_t)m * Cg + 2 * k2)     * 9 + t];
        if (2 * k2 + 1 < Cg) b = W[((size_t)m * Cg + 2 * k2 + 1) * 9 + t];
    }
    hp[idx] = pack_h2(a, b);
}

// ---------------- mma.m16n8k16 fp16 wrapper ----------------------------------
__device__ __forceinline__ void mma16816(float* d, const u32* a, const u32* b) {
    asm volatile(
        "mma.sync.aligned.m16n8k16.row.col.f32.f16.f16.f32 "
        "{%0,%1,%2,%3}, {%4,%5,%6,%7}, {%8,%9}, {%0,%1,%2,%3};"
        : "+f"(d[0]), "+f"(d[1]), "+f"(d[2]), "+f"(d[3])
        : "r"(a[0]), "r"(a[1]), "r"(a[2]), "r"(a[3]), "r"(b[0]), "r"(b[1]));
}

// =============================================================================
// 1x1 conv GEMM (K=256), pure fp16, double-buffered (R14 structure).
// If packOut != 0: fused BN + fp16-pair pack via shfl, NO fp32 output.
// Block: 128M x 128N, 8 warps, warp 64x32.  grid: (HW/128, Mtot/128, B).
// =============================================================================
__global__ __launch_bounds__(256) void gemm1x1_mma(
    const u32* __restrict__ wHp, int Mtot,
    const u32* __restrict__ aHp,
    float* __restrict__ out, u32* __restrict__ packOut,
    const float* __restrict__ bnp, int Cout, int use_bn)
{
    __shared__ u32 As[2][8][132];
    __shared__ u32 Bs[2][8][132];
    const int b    = blockIdx.z;
    const int m0   = blockIdx.y * 128, n0 = blockIdx.x * 128;
    const int tid  = threadIdx.x, wid = tid >> 5, lane = tid & 31;
    const int wm   = (wid >> 2) * 64, wn = (wid & 3) * 32;
    const int g    = lane >> 2, q = lane & 3;
    const u32* aB = aHp + (size_t)b * 128 * HW + n0;
    const u32* wB = wHp + m0;

    const int lrow = tid >> 5, lcol = (tid & 31) * 4;   // 1 uint4/thread per tile

    float acc[4][4][4];
#pragma unroll
    for (int i = 0; i < 4; i++)
#pragma unroll
        for (int j = 0; j < 4; j++)
#pragma unroll
            for (int r = 0; r < 4; r++) acc[i][j][r] = 0.f;

    uint4 rAv, rBv;
    auto loadg = [&](int kk) {
        rAv = *(const uint4*)&wB[(size_t)(kk * 8 + lrow) * Mtot + lcol];
        rBv = *(const uint4*)&aB[(size_t)(kk * 8 + lrow) * HW + lcol];
    };
    auto stores = [&](int st) {
        *(uint4*)&As[st][lrow][lcol] = rAv;
        *(uint4*)&Bs[st][lrow][lcol] = rBv;
    };

    loadg(0);
    stores(0);
    __syncthreads();

    for (int kk = 0; kk < 16; kk++) {
        const int cur = kk & 1;
        if (kk < 15) loadg(kk + 1);

        u32 aq[4][4], bq[4][2];
#pragma unroll
        for (int i = 0; i < 4; i++) {
            const int base = wm + i * 16 + g;
            aq[i][0] = As[cur][q][base];     aq[i][1] = As[cur][q][base + 8];
            aq[i][2] = As[cur][q + 4][base]; aq[i][3] = As[cur][q + 4][base + 8];
        }
#pragma unroll
        for (int j = 0; j < 4; j++) {
            const int nb = wn + j * 8 + g;
            bq[j][0] = Bs[cur][q][nb];
            bq[j][1] = Bs[cur][q + 4][nb];
        }
#pragma unroll
        for (int i = 0; i < 4; i++)
#pragma unroll
            for (int j = 0; j < 4; j++)
                mma16816(acc[i][j], aq[i], bq[j]);

        if (kk < 15) {
            stores(cur ^ 1);
            __syncthreads();
        }
    }

#pragma unroll
    for (int i = 0; i < 4; i++)
#pragma unroll
        for (int half = 0; half < 2; half++) {
            const int co = m0 + wm + i * 16 + g + half * 8;
            float scale = 1.f, shift = 0.f;
            if (use_bn) {
                const float gg = bnp[co],            be = bnp[Cout + co];
                const float mu = bnp[2 * Cout + co], va = bnp[3 * Cout + co];
                scale = gg * rsqrtf(va + 1e-5f);
                shift = be - mu * scale;
            }
            if (packOut) {
                // fused BN + pack: pair channel co (this lane) with co^1 (lane^4)
                const int c2 = co >> 1;
#pragma unroll
                for (int j = 0; j < 4; j++) {
                    float a0 = acc[i][j][half * 2]     * scale + shift;
                    float a1 = acc[i][j][half * 2 + 1] * scale + shift;
                    float p0 = __shfl_xor_sync(0xffffffffu, a0, 4);
                    float p1 = __shfl_xor_sync(0xffffffffu, a1, 4);
                    if ((g & 1) == 0) {
                        uint2 v = make_uint2(pack_h2(a0, p0), pack_h2(a1, p1));
                        *(uint2*)&packOut[((size_t)b * 128 + c2) * HW
                                          + n0 + wn + j * 8 + 2 * q] = v;
                    }
                }
            } else {
                float* o = out + ((size_t)b * Cout + co) * HW + n0 + wn + 2 * q;
#pragma unroll
                for (int j = 0; j < 4; j++) {
                    float2 v;
                    v.x = acc[i][j][half * 2]     * scale + shift;
                    v.y = acc[i][j][half * 2 + 1] * scale + shift;
                    *(float2*)&o[j * 8] = v;
                }
            }
        }
}

// =============================================================================
// Dilated 3x3 conv GEMM, all 3 groups in one launch (grid.y = group).
// Tap-outer, pure fp16, double-buffered (R14 structure).
// Block: 96M x 128N (one image row).  54 pipelined K-steps.
// grid: (H, 3, B), block 256.
// =============================================================================
__global__ __launch_bounds__(256) void dil_mma(
    const u32* __restrict__ wAll,    // [3][9][48][128]
    const u32* __restrict__ aHp,     // packed pre (fp16 pairs, channel-major)
    const float* __restrict__ bn0, const float* __restrict__ bn1,
    const float* __restrict__ bn2,
    float* __restrict__ out)
{
    const int grp = blockIdx.y;
    const int basePair   = (grp == 0) ? 0 : (grp == 1) ? 43 : 86;
    const int pairsValid = (grp == 2) ? 42 : 43;
    const int dil        = grp + 1;
    const int Cg         = (grp == 2) ? 84 : 86;
    const int coBase     = (grp == 0) ? 0 : (grp == 1) ? 86 : 172;
    const float* bnp     = (grp == 0) ? bn0 : (grp == 1) ? bn1 : bn2;
    const u32* wHp = wAll + (size_t)grp * (9 * 48 * 128);

    __shared__ u32 As[2][8][132];
    __shared__ u32 Bs[2][8][132];
    const int b    = blockIdx.z;
    const int h    = blockIdx.x;
    const int tid  = threadIdx.x, wid = tid >> 5, lane = tid & 31;
    const int wm   = (wid >> 2) * 48, wn = (wid & 3) * 32;
    const int g    = lane >> 2, q = lane & 3;
    const u32* aB = aHp + (size_t)b * 128 * HW;

    const int lrow = tid >> 5, lcol = (tid & 31) * 4;   // A: 1 uint4/thread
    const int bk0 = tid >> 7,  bn0v = tid & 127;        // B: 4 u32/thread

    float acc[3][4][4];
#pragma unroll
    for (int i = 0; i < 3; i++)
#pragma unroll
        for (int j = 0; j < 4; j++)
#pragma unroll
            for (int r = 0; r < 4; r++) acc[i][j][r] = 0.f;

    uint4 rAv;
    u32 rB[4];
    auto loadg = [&](int tap, int ks) {
        const int dy = tap / 3 - 1, dx = tap % 3 - 1;
        const int sh = h + dy * dil;
        const bool rowOk = (sh >= 0 && sh < H_);
        const int rowBase = tap * 48 + ks * 8;
        rAv = *(const uint4*)&wHp[(size_t)(rowBase + lrow) * 128 + lcol];
#pragma unroll
        for (int s = 0; s < 4; s++) {
            const int k2 = bk0 + s * 2;
            const int pr = ks * 8 + k2;
            const int sp = bn0v + dx * dil;
            u32 v = 0u;
            if (pr < pairsValid && rowOk && sp >= 0 && sp < W_)
                v = aB[(size_t)(basePair + pr) * HW + sh * W_ + sp];
            rB[s] = v;
        }
    };
    auto stores = [&](int st) {
        *(uint4*)&As[st][lrow][lcol] = rAv;
#pragma unroll
        for (int s = 0; s < 4; s++)
            Bs[st][bk0 + s * 2][bn0v] = rB[s];
    };

    loadg(0, 0);
    stores(0);
    __syncthreads();

    int tap = 0, ks = 0;
    for (int step = 0; step < 54; step++) {
        const int cur = step & 1;
        const int ntap = (ks == 5) ? tap + 1 : tap;
        const int nks  = (ks == 5) ? 0 : ks + 1;
        if (step < 53) loadg(ntap, nks);

        u32 aq[3][4], bq[4][2];
#pragma unroll
        for (int i = 0; i < 3; i++) {
            const int base = wm + i * 16 + g;
            aq[i][0] = As[cur][q][base];     aq[i][1] = As[cur][q][base + 8];
            aq[i][2] = As[cur][q + 4][base]; aq[i][3] = As[cur][q + 4][base + 8];
        }
#pragma unroll
        for (int j = 0; j < 4; j++) {
            const int nb = wn + j * 8 + g;
            bq[j][0] = Bs[cur][q][nb];
            bq[j][1] = Bs[cur][q + 4][nb];
        }
#pragma unroll
        for (int i = 0; i < 3; i++)
#pragma unroll
            for (int j = 0; j < 4; j++)
                mma16816(acc[i][j], aq[i], bq[j]);

        if (step < 53) {
            stores(cur ^ 1);
            __syncthreads();
        }
        tap = ntap; ks = nks;
    }

#pragma unroll
    for (int i = 0; i < 3; i++)
#pragma unroll
        for (int half = 0; half < 2; half++) {
            const int co = wm + i * 16 + g + half * 8;
            if (co < Cg) {
                const float gg = bnp[co],          be = bnp[Cg + co];
                const float mu = bnp[2 * Cg + co], va = bnp[3 * Cg + co];
                const float scale = gg * rsqrtf(va + 1e-5f);
                const float shift = be - mu * scale;
                float* o = out + ((size_t)b * C_ + coBase + co) * HW + h * W_ + wn + 2 * q;
#pragma unroll
                for (int j = 0; j < 4; j++) {
                    float2 v;
                    v.x = acc[i][j][half * 2]     * scale + shift;
                    v.y = acc[i][j][half * 2 + 1] * scale + shift;
                    *(float2*)&o[j * 8] = v;
                }
            }
        }
}

// =============================================================================
// Windowed attention (unchanged, verified).  grid: (B*256, NH), block 64
// =============================================================================
__global__ __launch_bounds__(64) void attn_kernel(
    const float* __restrict__ qkv, const float* __restrict__ rpb,
    float* __restrict__ out)
{
    const int win  = blockIdx.x;
    const int head = blockIdx.y;
    const int b    = win >> 8;
    const int wy   = (win >> 4) & 15;
    const int wx   = win & 15;
    const int i    = threadIdx.x;
    const int yi   = i >> 3, xi = i & 7;
    const int py   = wy * 8 + yi, px = wx * 8 + xi;

    __shared__ float ks[64][16];
    __shared__ float vs[64][16];
    __shared__ float bias_s[232];

    const size_t pix = (size_t)py * W_ + px;
    const float* qb  = qkv + ((size_t)b * 768 + head * DH) * HW + pix;

    float qv[16];
#pragma unroll
    for (int dd = 0; dd < 16; dd++) {
        qv[dd]    = qb[(size_t)dd * HW];
        ks[i][dd] = qb[(size_t)(256 + dd) * HW];
        vs[i][dd] = qb[(size_t)(512 + dd) * HW];
    }
    for (int t = i; t < 225; t += 64) bias_s[t] = rpb[t * NHD + head];
    __syncthreads();

    float s[64];
    float mx = -1e30f;
#pragma unroll
    for (int j = 0; j < 64; j++) {
        const float4* kr = (const float4*)&ks[j][0];
        float4 k0 = kr[0], k1 = kr[1], k2 = kr[2], k3 = kr[3];
        float dot = qv[0]  * k0.x + qv[1]  * k0.y + qv[2]  * k0.z + qv[3]  * k0.w
                  + qv[4]  * k1.x + qv[5]  * k1.y + qv[6]  * k1.z + qv[7]  * k1.w
                  + qv[8]  * k2.x + qv[9]  * k2.y + qv[10] * k2.z + qv[11] * k2.w
                  + qv[12] * k3.x + qv[13] * k3.y + qv[14] * k3.z + qv[15] * k3.w;
        const int yj = j >> 3, xj = j & 7;
        float val = dot * 0.25f + bias_s[(yi - yj + 7) * 15 + (xi - xj + 7)];
        s[j] = val;
        mx = fmaxf(mx, val);
    }
    float sum = 0.f;
#pragma unroll
    for (int j = 0; j < 64; j++) { float e = __expf(s[j] - mx); s[j] = e; sum += e; }
    const float inv = 1.f / sum;

    float4 o0 = {0, 0, 0, 0}, o1 = o0, o2 = o0, o3 = o0;
#pragma unroll
    for (int j = 0; j < 64; j++) {
        const float p = s[j];
        const float4* vr = (const float4*)&vs[j][0];
        float4 v0 = vr[0], v1 = vr[1], v2 = vr[2], v3 = vr[3];
        o0.x += p * v0.x; o0.y += p * v0.y; o0.z += p * v0.z; o0.w += p * v0.w;
        o1.x += p * v1.x; o1.y += p * v1.y; o1.z += p * v1.z; o1.w += p * v1.w;
        o2.x += p * v2.x; o2.y += p * v2.y; o2.z += p * v2.z; o2.w += p * v2.w;
        o3.x += p * v3.x; o3.y += p * v3.y; o3.z += p * v3.z; o3.w += p * v3.w;
    }

    float ov[16] = {o0.x, o0.y, o0.z, o0.w, o1.x, o1.y, o1.z, o1.w,
                    o2.x, o2.y, o2.z, o2.w, o3.x, o3.y, o3.z, o3.w};
    float* ob = out + ((size_t)b * C_ + head * DH) * HW + pix;
#pragma unroll
    for (int dd = 0; dd < 16; dd++) ob[(size_t)dd * HW] = ov[dd] * inv;
}

// =============================================================================
__global__ __launch_bounds__(256) void pooladd_kernel(
    const float* __restrict__ att, const float* __restrict__ loc,
    float* __restrict__ out)
{
    const size_t idx = (size_t)blockIdx.x * 256 + threadIdx.x;
    const int w = (int)(idx & (W_ - 1));
    const int h = (int)((idx >> 7) & (H_ - 1));
    const size_t bc = idx >> 14;
    const float* p = att + (bc << 14);
    float sx = 0.f, sy = 0.f;
#pragma unroll
    for (int t = -3; t <= 4; t++) {
        const int r = h + t;
        if (r >= 0 && r <= H_) { const int rr = (r == H_) ? H_ - 2 : r; sx += p[rr * W_ + w]; }
        const int c2 = w + t;
        if (c2 >= 0 && c2 <= W_) { const int cc = (c2 == W_) ? W_ - 2 : c2; sy += p[h * W_ + cc]; }
    }
    out[idx] = (sx + sy) * 0.125f + loc[idx];
}

// =============================================================================
__global__ __launch_bounds__(256) void dw_kernel(
    const float* __restrict__ in, const float* __restrict__ wdw,
    float* __restrict__ out)
{
    __shared__ float tile[23][48];
    __shared__ float wt[64];
    const int bc = blockIdx.z;
    const int h0 = blockIdx.y * 16, w0 = blockIdx.x * 16;
    const int tx = threadIdx.x, ty = threadIdx.y;
    const int tid = ty * 16 + tx;
    const float* p = in + (size_t)bc * HW;

    if (tid < 64) wt[tid] = wdw[(size_t)(bc & 255) * 64 + tid];
    for (int t = tid; t < 23 * 23; t += 256) {
        const int r = h0 - 3 + t / 23;
        const int s = w0 - 3 + t % 23;
        float v = 0.f;
        if (r >= 0 && r <= H_ && s >= 0 && s <= W_) {
            const int rr = (r == H_) ? H_ - 2 : r;
            const int ss = (s == W_) ? W_ - 2 : s;
            v = p[rr * W_ + ss];
        }
        tile[t / 23][t % 23] = v;
    }
    __syncthreads();

    float acc = 0.f;
#pragma unroll
    for (int u = 0; u < 8; u++)
#pragma unroll
        for (int v = 0; v < 8; v++)
            acc = fmaf(wt[u * 8 + v], tile[ty + u][tx + v], acc);
    out[(size_t)bc * HW + (h0 + ty) * W_ + w0 + tx] = acc;
}

// =============================================================================
extern "C" void kernel_launch(void* const* d_in, const int* in_sizes, int n_in,
                              void* d_out, int out_size)
{
    const float* x       = (const float*)d_in[0];
    const float* w_pre   = (const float*)d_in[1];
    const float* bn_pre  = (const float*)d_in[2];
    const float* w_l1    = (const float*)d_in[3];
    const float* bn_l1   = (const float*)d_in[4];
    const float* w_l2    = (const float*)d_in[5];
    const float* bn_l2   = (const float*)d_in[6];
    const float* w_l3    = (const float*)d_in[7];
    const float* bn_l3   = (const float*)d_in[8];
    const float* w_qkv   = (const float*)d_in[9];
    const float* rpb     = (const float*)d_in[10];
    const float* w_dw    = (const float*)d_in[11];
    const float* w_pw    = (const float*)d_in[12];
    const float* bn_proj = (const float*)d_in[13];
    float* out = (float*)d_out;

    float *bufA, *bufB, *bufC, *bufD;
    cudaGetSymbolAddress((void**)&bufA, g_bufA);
    cudaGetSymbolAddress((void**)&bufB, g_bufB);
    cudaGetSymbolAddress((void**)&bufC, g_bufC);
    cudaGetSymbolAddress((void**)&bufD, g_bufD);
    u32 *xH, *pH, *wPre, *wQkv, *wPw, *wDil;
    cudaGetSymbolAddress((void**)&xH,   g_xH);
    cudaGetSymbolAddress((void**)&pH,   g_pH);
    cudaGetSymbolAddress((void**)&wPre, g_wPreH);
    cudaGetSymbolAddress((void**)&wQkv, g_wQkvH);
    cudaGetSymbolAddress((void**)&wPw,  g_wPwH);
    cudaGetSymbolAddress((void**)&wDil, g_wDilH);

    float* loc  = bufB;
    float* qkvb = bufC;
    float* att  = bufD;
    float* mix  = bufA;
    float* dwo  = bufC;
    u32*   dH   = pH;    // stage-7 pack reuses pre-pack buffer (disjoint lifetime)

    const int DWALL = 3 * 9 * 48 * 128;
    const int packBlocks = (int)(APACK / 4 / 256);   // 16384

    // Launch order arranged so ncu (-s 5 -c 1) profiles launch #6 = dil_mma.
    // (1) pre weights
    pack_w1x1<<<(256 * 128 + 255) / 256, 256>>>(w_pre, wPre, 256);
    // (2) input activations
    pack_act<<<packBlocks, 256>>>(x, xH);
    // (3) pre 1x1 + BN, fused fp16 pack -> pH  (no fp32 stage buffer)
    gemm1x1_mma<<<dim3(HW / 128, 2, B_), 256>>>(wPre, 256, xH, nullptr, pH, bn_pre, 256, 1);
    // (4) dil weights (all groups, one launch)
    pack_wdil_all<<<(DWALL + 255) / 256, 256>>>(w_l1, w_l2, w_l3, wDil);
    // (5) qkv weights
    pack_w1x1<<<(768 * 128 + 255) / 256, 256>>>(w_qkv, wQkv, 768);
    // (6) dilated convs + BN, all 3 groups in one launch   <-- ncu lands here
    dil_mma<<<dim3(H_, 3, B_), 256>>>(wDil, pH, bn_l1, bn_l2, bn_l3, loc);
    // (7) qkv 1x1
    gemm1x1_mma<<<dim3(HW / 128, 6, B_), 256>>>(wQkv, 768, xH, qkvb, nullptr, bn_pre, 768, 0);
    // (8) attention
    attn_kernel<<<dim3(B_ * 256, NHD), 64>>>(qkvb, rpb, att);
    // (9) pool + add local
    pooladd_kernel<<<dim3((unsigned)((size_t)B_ * C_ * HW / 256)), 256>>>(att, loc, mix);
    // (10) depthwise 8x8
    dw_kernel<<<dim3(8, 8, B_ * C_), dim3(16, 16)>>>(mix, w_dw, dwo);
    // (11) pw weights
    pack_w1x1<<<(256 * 128 + 255) / 256, 256>>>(w_pw, wPw, 256);
    // (12) pack dwo
    pack_act<<<packBlocks, 256>>>(dwo, dH);
    // (13) pw 1x1 + BN -> final output
    gemm1x1_mma<<<dim3(HW / 128, 2, B_), 256>>>(wPw, 256, dH, out, nullptr, bn_proj, 256, 1);
}